// round 13
// baseline (speedup 1.0000x reference)
#include <cuda_runtime.h>
#include <cuda_fp16.h>
#include <stdint.h>

// HybridMixSTEDecoder: 5 disjoint-group GEMMs (27648x512 @ 512xN_i) + bias,
// scattered into out[b, tp*9+p, joint, c]. Groups disjoint -> count/div identity.
//
// Single-pass fp16 mma.sync (A, B RN-rounded fp16, fp32 accum; rel_err ~3e-4).
// 3-stage cp.async pipeline (K-chunk 32, one commit group per chunk,
// wait_group 1 -> 2 chunks in flight per CTA) at 3 CTAs/SM (24 warps) so
// consumer warps are both stall-free (no LDG in mainloop) and numerous.
// Grid (variant, m-block): CTAs sharing token rows are schedule-adjacent.

// Padded group rows: g0..g4 = 88,88,144,88,88 -> 496 rows of 512 fp16.
static __device__ __align__(16) __half g_Bh[496 * 512];

// ---------------- helpers ----------------
static __device__ __forceinline__ uint32_t s2u(const void* p) {
    uint32_t a;
    asm("{ .reg .u64 t; cvta.to.shared.u64 t, %1; cvt.u32.u64 %0, t; }"
        : "=r"(a) : "l"(p));
    return a;
}
static __device__ __forceinline__ uint32_t f16x2_rn(float lo, float hi) {
    uint32_t r; asm("cvt.rn.f16x2.f32 %0, %1, %2;" : "=r"(r) : "f"(hi), "f"(lo));
    return r;  // low half = lo, high half = hi
}
static __device__ __forceinline__ float4 lds128(uint32_t a) {
    float4 v;
    asm volatile("ld.shared.v4.f32 {%0,%1,%2,%3}, [%4];"
        : "=f"(v.x), "=f"(v.y), "=f"(v.z), "=f"(v.w) : "r"(a));
    return v;
}
static __device__ __forceinline__ void ldsm_x4(uint32_t* r, uint32_t addr) {
    asm volatile("ldmatrix.sync.aligned.m8n8.x4.shared.b16 {%0,%1,%2,%3}, [%4];"
        : "=r"(r[0]), "=r"(r[1]), "=r"(r[2]), "=r"(r[3]) : "r"(addr));
}
static __device__ __forceinline__ void ldsm_x2(uint32_t* r, uint32_t addr) {
    asm volatile("ldmatrix.sync.aligned.m8n8.x2.shared.b16 {%0,%1}, [%2];"
        : "=r"(r[0]), "=r"(r[1]) : "r"(addr));
}
static __device__ __forceinline__ void mma_f16(float* d, const uint32_t* a,
                                               const uint32_t* b) {
    asm volatile(
        "mma.sync.aligned.m16n8k16.row.col.f32.f16.f16.f32 "
        "{%0,%1,%2,%3}, {%4,%5,%6,%7}, {%8,%9}, {%0,%1,%2,%3};"
        : "+f"(d[0]), "+f"(d[1]), "+f"(d[2]), "+f"(d[3])
        : "r"(a[0]), "r"(a[1]), "r"(a[2]), "r"(a[3]), "r"(b[0]), "r"(b[1]));
}
static __device__ __forceinline__ void cp16(uint32_t dst, const void* src, int pred) {
    asm volatile(
        "{\n\t.reg .pred p;\n\tsetp.ne.b32 p, %0, 0;\n\t"
        "@p cp.async.cg.shared.global [%1], [%2], 16;\n\t}"
        :: "r"(pred), "r"(dst), "l"(src));
}

// ---------------- prep: W (f32) -> fp16, [n][512] with per-16k permute ------
// Thread handles 4 consecutive k (o = k&15 in {0,4,8,12}, t = o>>2):
//   halves (k,k+1)   -> eff positions (2t, 2t+1)
//   halves (k+2,k+3) -> eff positions (2t+8, 2t+9)
__global__ void __launch_bounds__(256) prep_B(
    const float* __restrict__ W0, const float* __restrict__ W1,
    const float* __restrict__ W2, const float* __restrict__ W3,
    const float* __restrict__ W4)
{
    int idx = blockIdx.x * 256 + threadIdx.x;   // one thread per (grow, k4)
    if (idx >= 496 * 128) return;
    int grow = idx >> 7;
    int k = (idx & 127) << 2;
    int g, n;
    if      (grow <  88) { g = 0; n = grow;       }
    else if (grow < 176) { g = 1; n = grow -  88; }
    else if (grow < 320) { g = 2; n = grow - 176; }
    else if (grow < 408) { g = 3; n = grow - 320; }
    else                 { g = 4; n = grow - 408; }
    const float* Wg = (g == 0) ? W0 : (g == 1) ? W1 : (g == 2) ? W2
                    : (g == 3) ? W3 : W4;
    int Ng = (g == 2) ? 135 : 81;

    float4 v = make_float4(0.f, 0.f, 0.f, 0.f);
    if (n < Ng) v = *(const float4*)(Wg + n * 512 + k);

    uint32_t h01 = f16x2_rn(v.x, v.y);
    uint32_t h23 = f16x2_rn(v.z, v.w);
    uint32_t* dst = (uint32_t*)g_Bh + grow * 256 + ((k & ~15) >> 1) + ((k >> 2) & 3);
    dst[0] = h01;   // eff (2t, 2t+1)
    dst[4] = h23;   // eff (2t+8, 2t+9)
}

// ---------------- fused core ----------------
// Smem: 3 A stages (raw f32, 128 rows x 128B, phys_u = u ^ ((row&1)<<2)),
// then 3 B stages (fp16, row pairs packed in 128B lines,
// phys = ((h<<2)|u) ^ (line&3)).
template<int NPAD, int GS, int CO>
static __device__ __forceinline__ void decode_core(
    const float* __restrict__ tokens,
    const __half* __restrict__ BhT,
    const float* __restrict__ bias,
    float* __restrict__ out,
    int gidx, int jb3)
{
    constexpr int NT    = NPAD / 8;
    constexpr int PAIRS = NT / 2;
    constexpr int ODD   = NT & 1;
    constexpr int NREAL = (GS == 5) ? 135 : 81;
    constexpr int ABS   = 16384;               // A stage bytes (128 x 128B)
    constexpr int BOFF  = 3 * ABS;             // B region base
    constexpr int BBS   = NPAD * 64;           // B stage bytes
    constexpr int NBOPS = NPAD * 4;            // B cp.async 16B ops per stage

    extern __shared__ char smem[];
    const uint32_t su = s2u(smem);

    const int tid  = threadIdx.x;
    const int wid  = tid >> 5;
    const int lane = tid & 31;

    const int m0 = blockIdx.y * 128;
    const float* Abase = tokens + (size_t)m0 * 2560 + gidx * 512;

    // ---- A producer geometry: 4 iters, row = (tid>>3) + 32*i, u = tid&7 ----
    const int prow = tid >> 3;
    const int pu   = tid & 7;
    const float* asrc0 = Abase + (size_t)prow * 2560 + pu * 4;
    const uint32_t adst0 = su + (uint32_t)(prow * 128
                         + ((pu ^ ((prow & 1) << 2)) << 4));

    // ---- B producer geometry: 2 iters (idx = tid, tid+256) ----
    const int bn0 = tid >> 2, bq0 = tid & 3;
    const int bn1 = (tid + 256) >> 2, bq1 = (tid + 256) & 3;
    const int bv0 = tid < NBOPS, bv1 = (tid + 256) < NBOPS;
    const __half* bsrc0 = BhT + bn0 * 512 + bq0 * 8;
    const __half* bsrc1 = BhT + bn1 * 512 + bq1 * 8;
    const uint32_t bdst0 = su + BOFF + (uint32_t)((bn0 >> 1) * 128
                         + (((((bn0 & 1) << 2) | bq0) ^ ((bn0 >> 1) & 3)) << 4));
    const uint32_t bdst1 = su + BOFF + (uint32_t)((bn1 >> 1) * 128
                         + (((((bn1 & 1) << 2) | bq1) ^ ((bn1 >> 1) & 3)) << 4));

    // ---- A consumer geometry (LDS.128) ----
    const int r1  = 16 * wid + (lane >> 2);
    const int tig = lane & 3;
    const int xr  = (r1 & 1) << 2;
    const uint32_t ac1 = su + (uint32_t)(r1 * 128);

    // ---- B consumer geometry (ldmatrix, packed row pairs) ----
    const int rBo = (lane & 7) + ((lane & 16) ? 8 : 0);
    const int kuB = (lane >> 3) & 1;
    const int lh  = rBo >> 1;            // line within 8-line tile
    const int hb  = (rBo & 1) << 2;      // half select bit
    const int bx  = lh & 3;              // xor term (constant per lane)
    const int lh2 = (lane & 7) >> 1;     // for the odd x2 tile
    const int hb2 = ((lane & 7) & 1) << 2;
    const int bx2 = lh2 & 3;

    float acc[NT][4];
    #pragma unroll
    for (int t = 0; t < NT; t++)
        #pragma unroll
        for (int q = 0; q < 4; q++) acc[t][q] = 0.f;

    // ---- prologue: chunks 0,1 as 2 commit groups ----
    #pragma unroll
    for (int c = 0; c < 2; c++) {
        #pragma unroll
        for (int i = 0; i < 4; i++)
            cp16(adst0 + c * ABS + i * 4096,
                 asrc0 + (size_t)i * 81920 + c * 32, 1);
        cp16(bdst0 + c * BBS, bsrc0 + c * 32, bv0);
        cp16(bdst1 + c * BBS, bsrc1 + c * 32, bv1);
        asm volatile("cp.async.commit_group;" ::: "memory");
    }

    #pragma unroll 1
    for (int kc = 0; kc < 16; kc++) {
        const int s = kc % 3;

        // chunk kc landed when <=1 group pending
        asm volatile("cp.async.wait_group 1;" ::: "memory");
        __syncthreads();

        // issue chunk kc+2 into stage (kc+2)%3 (= (kc-1)%3, readers done)
        {
            const int c = kc + 2;
            const int pred = (c < 16);
            const int s2 = c % 3;
            #pragma unroll
            for (int i = 0; i < 4; i++)
                cp16(adst0 + s2 * ABS + i * 4096,
                     asrc0 + (size_t)i * 81920 + c * 32, pred);
            cp16(bdst0 + s2 * BBS, bsrc0 + c * 32, pred && bv0);
            cp16(bdst1 + s2 * BBS, bsrc1 + c * 32, pred && bv1);
            asm volatile("cp.async.commit_group;" ::: "memory");
        }

        // compute on stage s (2 j-steps of k16)
        const uint32_t aS    = ac1 + (uint32_t)(s * ABS);
        const uint32_t bBase = su + BOFF + s * BBS;
        #pragma unroll
        for (int j = 0; j < 2; j++) {
            uint32_t u1 = (uint32_t)(((4 * j + tig) ^ xr) << 4);
            float4 v1 = lds128(aS + u1);
            float4 v2 = lds128(aS + 1024 + u1);    // row r1+8 (same parity)
            uint32_t ah[4];
            ah[0] = f16x2_rn(v1.x, v1.y);
            ah[2] = f16x2_rn(v1.z, v1.w);
            ah[1] = f16x2_rn(v2.x, v2.y);
            ah[3] = f16x2_rn(v2.z, v2.w);
            const int u = 2 * j + kuB;
            const uint32_t bo = (uint32_t)(lh * 128 + (((hb | u) ^ bx) << 4));
            #pragma unroll
            for (int p = 0; p < PAIRS; p++) {
                uint32_t bh[4];
                ldsm_x4(bh, bBase + p * 1024 + bo);
                mma_f16(acc[2 * p],     ah, bh);
                mma_f16(acc[2 * p + 1], ah, bh + 2);
            }
            if (ODD) {
                uint32_t bo2 = (uint32_t)(PAIRS * 1024 + lh2 * 128
                             + (((hb2 | u) ^ bx2) << 4));
                uint32_t bh[2];
                ldsm_x2(bh, bBase + bo2);
                mma_f16(acc[NT - 1], ah, bh);
            }
        }
    }

    // ---- epilogue: bias + scatter ----
    const int g = lane >> 2;

    int   coff[NT][2];
    float cb[NT][2];
    #pragma unroll
    for (int t = 0; t < NT; t++) {
        #pragma unroll
        for (int h = 0; h < 2; h++) {
            int o = CO + 8 * t + 2 * tig + h;
            if (o < NREAL) {
                int p   = o / (GS * 3);
                int rem = o - p * (GS * 3);
                int joff = (GS == 5) ? ((rem < 3) ? rem : rem + 18) : (jb3 + rem);
                coff[t][h] = p * 51 + joff;
                cb[t][h]   = bias[o];
            } else {
                coff[t][h] = -1;
                cb[t][h]   = 0.f;
            }
        }
    }

    #pragma unroll
    for (int half = 0; half < 2; half++) {
        int m  = m0 + 16 * wid + g + 8 * half;
        int b  = m / 27;
        int tp = m - b * 27;
        size_t obase = (size_t)b * 12393 + (size_t)tp * 459;
        #pragma unroll
        for (int t = 0; t < NT; t++) {
            float v0 = acc[t][2 * half];
            float v1 = acc[t][2 * half + 1];
            if (coff[t][0] >= 0) out[obase + coff[t][0]] = v0 + cb[t][0];
            if (coff[t][1] >= 0) out[obase + coff[t][1]] = v1 + cb[t][1];
        }
    }
}

// One fused kernel. blockIdx.x = variant: 0..3 -> groups 0,1,3,4 (NPAD=88);
// 4,5 -> group 2 halves (NPAD=72). blockIdx.y = m-block (same token rows
// across all 6 variants -> L2 reuse for g2 double-read + output merging).
__global__ void __launch_bounds__(256, 3) dec_all(
    const float* __restrict__ tokens,
    const float* __restrict__ b0, const float* __restrict__ b1,
    const float* __restrict__ b2, const float* __restrict__ b3,
    const float* __restrict__ b4,
    float* __restrict__ out)
{
    int y = blockIdx.x;
    if (y < 4) {
        int rowbase, gidx, jb3;
        const float* bias;
        switch (y) {
            case 0:  rowbase = 0;   gidx = 0; jb3 = 3;  bias = b0; break;
            case 1:  rowbase = 88;  gidx = 1; jb3 = 12; bias = b1; break;
            case 2:  rowbase = 320; gidx = 3; jb3 = 33; bias = b3; break;
            default: rowbase = 408; gidx = 4; jb3 = 42; bias = b4; break;
        }
        decode_core<88, 3, 0>(tokens, g_Bh + rowbase * 512, bias, out, gidx, jb3);
    } else if (y == 4) {
        decode_core<72, 5, 0>(tokens, g_Bh + 176 * 512, b2, out, 2, 0);
    } else {
        decode_core<72, 5, 72>(tokens, g_Bh + 248 * 512, b2, out, 2, 0);
    }
}

extern "C" void kernel_launch(void* const* d_in, const int* in_sizes, int n_in,
                              void* d_out, int out_size) {
    const float* tokens = (const float*)d_in[0];
    const float* W[5];
    const float* B[5];
    for (int i = 0; i < 5; i++) {
        W[i] = (const float*)d_in[1 + 2 * i];
        B[i] = (const float*)d_in[2 + 2 * i];
    }
    float* out = (float*)d_out;

    // dyn smem: 3 A stages (16KB) + 3 B stages (<=5632B) = 66048 B
    // -> 3 CTAs/SM (198144 <= 233472).
    const int smem_sz = 3 * 16384 + 3 * 88 * 64;
    cudaFuncSetAttribute(dec_all, cudaFuncAttributeMaxDynamicSharedMemorySize, smem_sz);

    prep_B<<<(496 * 128 + 255) / 256, 256>>>(W[0], W[1], W[2], W[3], W[4]);
    dec_all<<<dim3(6, 216), 256, smem_sz>>>(tokens, B[0], B[1], B[2], B[3], B[4], out);
}

// round 14
// speedup vs baseline: 1.4639x; 1.4639x over previous
#include <cuda_runtime.h>
#include <cuda_fp16.h>
#include <stdint.h>

// HybridMixSTEDecoder: 5 disjoint-group GEMMs (27648x512 @ 512xN_i) + bias,
// scattered into out[b, tp*9+p, joint, c]. Groups disjoint -> count/div identity.
//
// Single-pass fp16 mma.sync (A, B RN-rounded fp16, fp32 accum; rel_err ~3e-4).
// A fragments direct from gmem (full-chunk register buffer, k-permuted).
// B pre-tiled in prep_B into LINE-PACKED ldmatrix tiles: one 128B line = one
// 8x8 tile (8 n-rows x 16B k-unit) -> ldsm_x4 touches 4 lines (wavefront
// floor) instead of 16. No swizzle needed (each ldmatrix phase = one line).

// Regions (padded): v0..v3 = g0,g1,g3,g4 (NPAD 88); v4,v5 = g2 halves (NPAD 72).
// Region u32 sizes: 88*256 = 22528; 72*256 = 18432. Total 126976 u32 (496 KB).
static __device__ __align__(16) uint32_t g_B[126976];

// ---------------- helpers ----------------
static __device__ __forceinline__ uint32_t s2u(const void* p) {
    uint32_t a;
    asm("{ .reg .u64 t; cvta.to.shared.u64 t, %1; cvt.u32.u64 %0, t; }"
        : "=r"(a) : "l"(p));
    return a;
}
static __device__ __forceinline__ uint32_t f16x2_rn(float lo, float hi) {
    uint32_t r; asm("cvt.rn.f16x2.f32 %0, %1, %2;" : "=r"(r) : "f"(hi), "f"(lo));
    return r;  // low half = lo, high half = hi
}
static __device__ __forceinline__ void ldsm_x4(uint32_t* r, uint32_t addr) {
    asm volatile("ldmatrix.sync.aligned.m8n8.x4.shared.b16 {%0,%1,%2,%3}, [%4];"
        : "=r"(r[0]), "=r"(r[1]), "=r"(r[2]), "=r"(r[3]) : "r"(addr));
}
static __device__ __forceinline__ void ldsm_x2(uint32_t* r, uint32_t addr) {
    asm volatile("ldmatrix.sync.aligned.m8n8.x2.shared.b16 {%0,%1}, [%2];"
        : "=r"(r[0]), "=r"(r[1]) : "r"(addr));
}
static __device__ __forceinline__ void mma_f16(float* d, const uint32_t* a,
                                               const uint32_t* b) {
    asm volatile(
        "mma.sync.aligned.m16n8k16.row.col.f32.f16.f16.f32 "
        "{%0,%1,%2,%3}, {%4,%5,%6,%7}, {%8,%9}, {%0,%1,%2,%3};"
        : "+f"(d[0]), "+f"(d[1]), "+f"(d[2]), "+f"(d[3])
        : "r"(a[0]), "r"(a[1]), "r"(a[2]), "r"(a[3]), "r"(b[0]), "r"(b[1]));
}
static __device__ __forceinline__ void cp16(uint32_t dst, const void* src, int pred) {
    asm volatile(
        "{\n\t.reg .pred p;\n\tsetp.ne.b32 p, %0, 0;\n\t"
        "@p cp.async.cg.shared.global [%1], [%2], 16;\n\t}"
        :: "r"(pred), "r"(dst), "l"(src));
}

// ---------------- prep: W (f32) -> fp16 line-packed ldmatrix tiles ----------
// Content per (n, k4-block) identical to the proven k-permute:
//   h01 = f16(k, k+1)  -> unit u0 = 2j, slot t
//   h23 = f16(k+2,k+3) -> unit u1 = 2j+1, slot t
// with j = (k>>4)&3, t = (k>>2)&3, kc = k>>6.
// dst u32 = base_v + kc*(NPAD*32) + (n>>3)*256 + u*32 + (n&7)*4 + t.
__global__ void __launch_bounds__(256) prep_B(
    const float* __restrict__ W0, const float* __restrict__ W1,
    const float* __restrict__ W2, const float* __restrict__ W3,
    const float* __restrict__ W4)
{
    int idx = blockIdx.x * 256 + threadIdx.x;   // one thread per (grow, k4)
    if (idx >= 496 * 128) return;
    int grow = idx >> 7;
    int k = (idx & 127) << 2;

    const float* Wg;
    int n, n_src, npad, base, Ng;
    if (grow < 352) {                        // v0..v3: NPAD 88
        int v = grow / 88;
        n = grow - v * 88;
        n_src = n;
        npad = 88;
        base = v * 22528;
        Ng = 81;
        Wg = (v == 0) ? W0 : (v == 1) ? W1 : (v == 2) ? W3 : W4;
    } else if (grow < 424) {                 // v4: g2 half 0
        n = grow - 352; n_src = n;
        npad = 72; base = 90112; Ng = 135; Wg = W2;
    } else {                                 // v5: g2 half 1
        n = grow - 424; n_src = n + 72;
        npad = 72; base = 108544; Ng = 135; Wg = W2;
    }

    float4 v4v = make_float4(0.f, 0.f, 0.f, 0.f);
    if (n_src < Ng) v4v = *(const float4*)(Wg + n_src * 512 + k);

    uint32_t h01 = f16x2_rn(v4v.x, v4v.y);
    uint32_t h23 = f16x2_rn(v4v.z, v4v.w);

    int kc = k >> 6, j = (k >> 4) & 3, t = (k >> 2) & 3;
    uint32_t* dst = g_B + base + kc * (npad * 32) + (n >> 3) * 256
                  + (2 * j) * 32 + (n & 7) * 4 + t;
    dst[0]  = h01;   // unit 2j
    dst[32] = h23;   // unit 2j+1
}

// ---------------- fused core ----------------
// Smem: two B stages of NPAD*128 bytes, contents already in final tile order
// (contiguous copy from g_B). A never touches smem (register chunk buffer).
template<int NPAD, int GS, int CO>
static __device__ __forceinline__ void decode_core(
    const float* __restrict__ tokens,
    const uint32_t* __restrict__ Breg,     // region base in g_B
    const float* __restrict__ bias,
    float* __restrict__ out,
    int gidx, int jb3)
{
    constexpr int NT    = NPAD / 8;
    constexpr int PAIRS = NT / 2;
    constexpr int ODD   = NT & 1;
    constexpr int NREAL = (GS == 5) ? 135 : 81;
    constexpr int BB    = NPAD * 128;          // B stage bytes (one chunk)
    constexpr int NB8   = NPAD * 8;            // cp.async 16B ops
    constexpr int CPIT  = (NB8 + 255) / 256;

    extern __shared__ char smem[];
    const uint32_t su = s2u(smem);

    const int tid  = threadIdx.x;
    const int wid  = tid >> 5;
    const int lane = tid & 31;

    const int m0 = blockIdx.y * 128;

    // A direct-load geometry with the k-permute: lane (r = lane>>2, tig = lane&3)
    // loads float4 at (row r, k = 16j + 4*tig) and (row r+8, same k).
    const float* aw = tokens
        + (size_t)(m0 + 16 * wid + (lane >> 2)) * 2560
        + gidx * 512 + (lane & 3) * 4;

    // B ldmatrix lane addressing (line-packed tiles):
    //   x4 addr = bBase + p*2048 + j*256 + bl
    //   bl = ((lane>>4)&1)*1024 + ((lane>>3)&1)*128 + (lane&7)*16
    const uint32_t bl  = (uint32_t)((((lane >> 4) & 1) << 10)
                       + (((lane >> 3) & 1) << 7) + ((lane & 7) << 4));
    //   x2 (odd tile) addr = bBase + PAIRS*2048 + j*256 + bl2 (lanes 0-15)
    const uint32_t bl2 = (uint32_t)((((lane >> 3) & 1) << 7) + ((lane & 7) << 4));

    float acc[NT][4];
    #pragma unroll
    for (int t = 0; t < NT; t++)
        #pragma unroll
        for (int q = 0; q < 4; q++) acc[t][q] = 0.f;

    // Full-chunk A register buffer (compile-time indices only).
    float4 ra[8];
    #pragma unroll
    for (int j = 0; j < 4; j++) {
        ra[2 * j]     = *(const float4*)(aw + j * 16);
        ra[2 * j + 1] = *(const float4*)(aw + j * 16 + 20480);
    }
    // B(0) cp.async: contiguous copy (layout pre-baked in prep_B)
    {
        const char* bsrc = (const char*)Breg;
        #pragma unroll
        for (int jj = 0; jj < CPIT; jj++) {
            int idx = tid + jj * 256;
            cp16(su + (uint32_t)(idx * 16), bsrc + idx * 16, idx < NB8);
        }
        asm volatile("cp.async.commit_group;" ::: "memory");
    }

    #pragma unroll 1
    for (int kc = 0; kc < 8; kc++) {
        const int s = kc & 1;

        // B(kc) ready; publish stage s
        asm volatile("cp.async.wait_group 0;" ::: "memory");
        __syncthreads();
        // issue B(kc+1) into stage s^1 (all warps are past reads of s^1)
        if (kc < 7) {
            const uint32_t bdst = su + (uint32_t)((s ^ 1) * BB);
            const char* bsrc = (const char*)(Breg + (kc + 1) * (NPAD * 32));
            #pragma unroll
            for (int jj = 0; jj < CPIT; jj++) {
                int idx = tid + jj * 256;
                cp16(bdst + (uint32_t)(idx * 16), bsrc + idx * 16, idx < NB8);
            }
            asm volatile("cp.async.commit_group;" ::: "memory");
        }

        const uint32_t bBase = su + (uint32_t)(s * BB);
        #pragma unroll
        for (int j = 0; j < 4; j++) {
            // convert current A fragment (permuted layout: float4 -> a0,a2)
            uint32_t ah[4];
            ah[0] = f16x2_rn(ra[2 * j].x,     ra[2 * j].y);
            ah[2] = f16x2_rn(ra[2 * j].z,     ra[2 * j].w);
            ah[1] = f16x2_rn(ra[2 * j + 1].x, ra[2 * j + 1].y);
            ah[3] = f16x2_rn(ra[2 * j + 1].z, ra[2 * j + 1].w);
            // refill this slot from chunk kc+1 (lookahead ~4 j-steps)
            if (kc < 7) {
                const float* ap = aw + (kc + 1) * 64 + j * 16;
                ra[2 * j]     = *(const float4*)(ap);
                ra[2 * j + 1] = *(const float4*)(ap + 20480);
            }
            // B fragments + MMAs (line-packed tiles, wavefront-minimal)
            const uint32_t bj = bBase + (uint32_t)(j * 256);
            #pragma unroll
            for (int p = 0; p < PAIRS; p++) {
                uint32_t bh[4];
                ldsm_x4(bh, bj + (uint32_t)(p * 2048) + bl);
                mma_f16(acc[2 * p],     ah, bh);
                mma_f16(acc[2 * p + 1], ah, bh + 2);
            }
            if (ODD) {
                uint32_t bh[2];
                ldsm_x2(bh, bj + (uint32_t)(PAIRS * 2048) + bl2);
                mma_f16(acc[NT - 1], ah, bh);
            }
        }
    }

    // ---- epilogue: bias + scatter ----
    const int g   = lane >> 2;
    const int tig = lane & 3;

    int   coff[NT][2];
    float cb[NT][2];
    #pragma unroll
    for (int t = 0; t < NT; t++) {
        #pragma unroll
        for (int h = 0; h < 2; h++) {
            int o = CO + 8 * t + 2 * tig + h;
            if (o < NREAL) {
                int p   = o / (GS * 3);
                int rem = o - p * (GS * 3);
                int joff = (GS == 5) ? ((rem < 3) ? rem : rem + 18) : (jb3 + rem);
                coff[t][h] = p * 51 + joff;
                cb[t][h]   = bias[o];
            } else {
                coff[t][h] = -1;
                cb[t][h]   = 0.f;
            }
        }
    }

    #pragma unroll
    for (int half = 0; half < 2; half++) {
        int m  = m0 + 16 * wid + g + 8 * half;
        int b  = m / 27;
        int tp = m - b * 27;
        size_t obase = (size_t)b * 12393 + (size_t)tp * 459;
        #pragma unroll
        for (int t = 0; t < NT; t++) {
            float v0 = acc[t][2 * half];
            float v1 = acc[t][2 * half + 1];
            if (coff[t][0] >= 0) out[obase + coff[t][0]] = v0 + cb[t][0];
            if (coff[t][1] >= 0) out[obase + coff[t][1]] = v1 + cb[t][1];
        }
    }
}

// One fused kernel. blockIdx.x = variant: 0..3 -> groups 0,1,3,4 (NPAD=88);
// 4,5 -> group 2 halves (NPAD=72). blockIdx.y = m-block (same token rows
// across all 6 variants -> L2 reuse for g2 double-read + output merging).
__global__ void __launch_bounds__(256, 2) dec_all(
    const float* __restrict__ tokens,
    const float* __restrict__ b0, const float* __restrict__ b1,
    const float* __restrict__ b2, const float* __restrict__ b3,
    const float* __restrict__ b4,
    float* __restrict__ out)
{
    int y = blockIdx.x;
    if (y < 4) {
        int gidx, jb3;
        const float* bias;
        switch (y) {
            case 0:  gidx = 0; jb3 = 3;  bias = b0; break;
            case 1:  gidx = 1; jb3 = 12; bias = b1; break;
            case 2:  gidx = 3; jb3 = 33; bias = b3; break;
            default: gidx = 4; jb3 = 42; bias = b4; break;
        }
        decode_core<88, 3, 0>(tokens, g_B + y * 22528, bias, out, gidx, jb3);
    } else if (y == 4) {
        decode_core<72, 5, 0>(tokens, g_B + 90112, b2, out, 2, 0);
    } else {
        decode_core<72, 5, 72>(tokens, g_B + 108544, b2, out, 2, 0);
    }
}

extern "C" void kernel_launch(void* const* d_in, const int* in_sizes, int n_in,
                              void* d_out, int out_size) {
    const float* tokens = (const float*)d_in[0];
    const float* W[5];
    const float* B[5];
    for (int i = 0; i < 5; i++) {
        W[i] = (const float*)d_in[1 + 2 * i];
        B[i] = (const float*)d_in[2 + 2 * i];
    }
    float* out = (float*)d_out;

    // dyn smem: 2 B stages of 88*128 = 22528 bytes max
    const int smem_sz = 2 * 88 * 128;

    prep_B<<<(496 * 128 + 255) / 256, 256>>>(W[0], W[1], W[2], W[3], W[4]);
    dec_all<<<dim3(6, 216), 256, smem_sz>>>(tokens, B[0], B[1], B[2], B[3], B[4], out);
}